// round 10
// baseline (speedup 1.0000x reference)
#include <cuda_runtime.h>
#include <cstdint>
#include <math.h>

// Problem dims (fixed per reference)
#define T_TOK 8192
#define H_DIM 4096
#define I_DIM 11008
#define KW_H (H_DIM / 4)   // 1024 packed words over K=H
#define KW_I (I_DIM / 4)   // 2752 packed words over K=I

// ---------------- scratch (device globals: no allocations allowed) ----------------
__device__ int g_qx[T_TOK * KW_H];                 //  33.5 MB  quantized/packed x
__device__ int g_wg[I_DIM * KW_H];                 //  45 MB    packed w_gate
__device__ int g_wu[I_DIM * KW_H];                 //  45 MB    packed w_up
__device__ int g_wd[H_DIM * KW_I];                 //  45 MB    packed w_down
__device__ int g_gate[T_TOK * I_DIM];              // 361 MB    gate int32 accum
__device__ int g_up[T_TOK * I_DIM];                // 361 MB    up   int32 accum
__device__ int g_qh[T_TOK * KW_I];                 //  90 MB    quantized/packed h

// ---------------- XLA-replica tanh (unfused, GPU elemental emitter) -------------
// logistic(x) = 0.5 + 0.5*tanh(0.5*x); tanh f32 = XLA EmitTanh rational poly,
// clamp +-7.90531, |x| < 0.0004 -> x.  Mul/add unfused.
__device__ __forceinline__ float xla_tanh(float x) {
    const float kMax = 7.90531110763549805f;
    float xc = fminf(fmaxf(x, -kMax), kMax);
    float x2 = __fmul_rn(xc, xc);
    float p = -2.76076847742355e-16f;
    p = __fadd_rn(__fmul_rn(p, x2), 2.00018790482477e-13f);
    p = __fadd_rn(__fmul_rn(p, x2), -8.60467152213735e-11f);
    p = __fadd_rn(__fmul_rn(p, x2), 5.12229709037114e-08f);
    p = __fadd_rn(__fmul_rn(p, x2), 1.48572235717979e-05f);
    p = __fadd_rn(__fmul_rn(p, x2), 6.37261928875436e-04f);
    p = __fadd_rn(__fmul_rn(p, x2), 4.89352455891786e-03f);
    p = __fmul_rn(xc, p);
    float q = 1.19825839466702e-06f;
    q = __fadd_rn(__fmul_rn(q, x2), 1.18534705686654e-04f);
    q = __fadd_rn(__fmul_rn(q, x2), 2.26843463243900e-03f);
    q = __fadd_rn(__fmul_rn(q, x2), 4.89352518554385e-03f);
    float t = __fdiv_rn(p, q);
    return (fabsf(x) < 0.0004f) ? x : t;
}

__device__ __forceinline__ float ref_silu(float g) {
    float t   = xla_tanh(__fmul_rn(0.5f, g));
    float sig = __fadd_rn(0.5f, __fmul_rn(0.5f, t));
    return __fmul_rn(g, sig);   // silu = x * sigmoid(x)
}

// reference dequant: dot * s + b with SEPARATE mul and add (unfused)
__device__ __forceinline__ float ref_deq(float acc, float s, float b) {
    return __fadd_rn(__fmul_rn(acc, s), b);
}

// quantize via XLA rendition: divide(x, bcast(s)) -> multiply(x, bcast(1/s))
__device__ __forceinline__ int ref_quant(float v, float inv_s) {
    float r = rintf(__fmul_rn(v, inv_s));
    return (int)fminf(fmaxf(r, -127.f), 127.f);
}

// ---------------- quantize + pack x (reciprocal-multiply rendition) ------------
__global__ void quant_pack_x_kernel(const float* __restrict__ x,
                                    const float* __restrict__ scale_p,
                                    int* __restrict__ qx, int n4) {
    int idx = blockIdx.x * 256 + threadIdx.x;
    if (idx >= n4) return;
    float inv_s = __fdiv_rn(1.0f, __ldg(scale_p));   // XLA: one scalar divide
    float4 v = reinterpret_cast<const float4*>(x)[idx];
    int q0 = ref_quant(v.x, inv_s);
    int q1 = ref_quant(v.y, inv_s);
    int q2 = ref_quant(v.z, inv_s);
    int q3 = ref_quant(v.w, inv_s);
    qx[idx] = (q0 & 255) | ((q1 & 255) << 8) | ((q2 & 255) << 16) | (q3 << 24);
}

// ---------------- pack int32 weights -> int8x4 words ----------------
__global__ void pack_w_kernel(const int* __restrict__ w, int* __restrict__ wp, int n4) {
    int idx = blockIdx.x * 256 + threadIdx.x;
    if (idx >= n4) return;
    int4 v = reinterpret_cast<const int4*>(w)[idx];
    wp[idx] = (v.x & 255) | ((v.y & 255) << 8) | ((v.z & 255) << 16) | (v.w << 24);
}

// ---------------- int8 GEMM: C[M,N] = A[M,K] . B[N,K]^T (both K-packed words) ---
// Block tile 128x128, K-step 64 (16 words). 256 threads, 8x8 micro-tile/thread.
// EPI==0: write raw int32 accum to Ci.  EPI==1: fp32 dequant+bias to Cf.
template <int EPI>
__global__ void __launch_bounds__(256, 2)
gemm_s8_kernel(const int* __restrict__ A, const int* __restrict__ B,
               int Kw, int N,
               int* __restrict__ Ci, float* __restrict__ Cf,
               const float* __restrict__ wsc, const float* __restrict__ bias,
               const float* __restrict__ ascale) {
    __shared__ int As[2][16][128];
    __shared__ int Bs[2][16][128];

    const int tid = threadIdx.x;
    const int tx  = tid & 15;      // 0..15  -> N micro index
    const int ty  = tid >> 4;      // 0..15  -> M micro index
    const int bm  = blockIdx.y << 7;
    const int bn  = blockIdx.x << 7;

    // global loader mapping: 2 threads per row, 8 words each
    const int row = tid >> 1;            // 0..127
    const int kg  = (tid & 1) << 3;      // 0 or 8
    const int* Ap = A + (bm + row) * Kw + kg;
    const int* Bp = B + (bn + row) * Kw + kg;

    int acc[8][8];
#pragma unroll
    for (int i = 0; i < 8; ++i)
#pragma unroll
        for (int j = 0; j < 8; ++j) acc[i][j] = 0;

    const int nsteps = Kw >> 4;

    // prologue: tile 0 -> smem stage 0
    int4 a0 = *reinterpret_cast<const int4*>(Ap);
    int4 a1 = *reinterpret_cast<const int4*>(Ap + 4);
    int4 b0 = *reinterpret_cast<const int4*>(Bp);
    int4 b1 = *reinterpret_cast<const int4*>(Bp + 4);
    As[0][kg + 0][row] = a0.x; As[0][kg + 1][row] = a0.y;
    As[0][kg + 2][row] = a0.z; As[0][kg + 3][row] = a0.w;
    As[0][kg + 4][row] = a1.x; As[0][kg + 5][row] = a1.y;
    As[0][kg + 6][row] = a1.z; As[0][kg + 7][row] = a1.w;
    Bs[0][kg + 0][row] = b0.x; Bs[0][kg + 1][row] = b0.y;
    Bs[0][kg + 2][row] = b0.z; Bs[0][kg + 3][row] = b0.w;
    Bs[0][kg + 4][row] = b1.x; Bs[0][kg + 5][row] = b1.y;
    Bs[0][kg + 6][row] = b1.z; Bs[0][kg + 7][row] = b1.w;
    __syncthreads();

    for (int step = 0; step < nsteps; ++step) {
        const int buf = step & 1;
        const bool more = (step + 1 < nsteps);
        if (more) {
            const int* Ap2 = Ap + ((step + 1) << 4);
            const int* Bp2 = Bp + ((step + 1) << 4);
            a0 = *reinterpret_cast<const int4*>(Ap2);
            a1 = *reinterpret_cast<const int4*>(Ap2 + 4);
            b0 = *reinterpret_cast<const int4*>(Bp2);
            b1 = *reinterpret_cast<const int4*>(Bp2 + 4);
        }
#pragma unroll
        for (int kw = 0; kw < 16; ++kw) {
            int af[8], bf[8];
#pragma unroll
            for (int i = 0; i < 8; ++i) af[i] = As[buf][kw][ty + (i << 4)];
#pragma unroll
            for (int j = 0; j < 8; ++j) bf[j] = Bs[buf][kw][tx + (j << 4)];
#pragma unroll
            for (int i = 0; i < 8; ++i)
#pragma unroll
                for (int j = 0; j < 8; ++j)
                    acc[i][j] = __dp4a(af[i], bf[j], acc[i][j]);
        }
        if (more) {
            const int nb = buf ^ 1;
            As[nb][kg + 0][row] = a0.x; As[nb][kg + 1][row] = a0.y;
            As[nb][kg + 2][row] = a0.z; As[nb][kg + 3][row] = a0.w;
            As[nb][kg + 4][row] = a1.x; As[nb][kg + 5][row] = a1.y;
            As[nb][kg + 6][row] = a1.z; As[nb][kg + 7][row] = a1.w;
            Bs[nb][kg + 0][row] = b0.x; Bs[nb][kg + 1][row] = b0.y;
            Bs[nb][kg + 2][row] = b0.z; Bs[nb][kg + 3][row] = b0.w;
            Bs[nb][kg + 4][row] = b1.x; Bs[nb][kg + 5][row] = b1.y;
            Bs[nb][kg + 6][row] = b1.z; Bs[nb][kg + 7][row] = b1.w;
        }
        __syncthreads();
    }

    if (EPI == 0) {
#pragma unroll
        for (int i = 0; i < 8; ++i) {
            const int r = bm + ty + (i << 4);
#pragma unroll
            for (int j = 0; j < 8; ++j)
                Ci[r * N + bn + tx + (j << 4)] = acc[i][j];
        }
    } else {
        const float asd = __ldg(ascale);
        float s[8], bb[8];
#pragma unroll
        for (int j = 0; j < 8; ++j) {
            const int c = bn + tx + (j << 4);
            s[j]  = __fmul_rn(asd, __ldg(wsc + c));
            bb[j] = __ldg(bias + c);
        }
#pragma unroll
        for (int i = 0; i < 8; ++i) {
            const int r = bm + ty + (i << 4);
#pragma unroll
            for (int j = 0; j < 8; ++j)
                Cf[r * N + bn + tx + (j << 4)] = ref_deq((float)acc[i][j], s[j], bb[j]);
        }
    }
}

// ---------------- SwiGLU + requantize + pack (reciprocal-multiply requant) -----
__global__ void swiglu_quant_kernel(const int* __restrict__ gacc, const int* __restrict__ uacc,
                                    const float* __restrict__ wsg, const float* __restrict__ wsu,
                                    const float* __restrict__ bg, const float* __restrict__ bu,
                                    const float* __restrict__ asg_p, const float* __restrict__ asd_p,
                                    int* __restrict__ qh) {
    const int i4 = blockIdx.x * 256 + threadIdx.x;
    if (i4 >= KW_I) return;
    const int t = blockIdx.y;
    const int widx = t * KW_I + i4;

    const float asg = __ldg(asg_p);
    const float inv_asd = __fdiv_rn(1.0f, __ldg(asd_p));  // XLA: scalar divide once

    int4 g4 = reinterpret_cast<const int4*>(gacc)[widx];
    int4 u4 = reinterpret_cast<const int4*>(uacc)[widx];
    float4 sg = reinterpret_cast<const float4*>(wsg)[i4];
    float4 su = reinterpret_cast<const float4*>(wsu)[i4];
    float4 bgv = reinterpret_cast<const float4*>(bg)[i4];
    float4 buv = reinterpret_cast<const float4*>(bu)[i4];

    // gate = dot * (asg*ws) + b  (unfused, XLA GPU emitter rendition)
    float g0 = ref_deq((float)g4.x, __fmul_rn(asg, sg.x), bgv.x);
    float g1 = ref_deq((float)g4.y, __fmul_rn(asg, sg.y), bgv.y);
    float g2 = ref_deq((float)g4.z, __fmul_rn(asg, sg.z), bgv.z);
    float g3 = ref_deq((float)g4.w, __fmul_rn(asg, sg.w), bgv.w);
    float u0 = ref_deq((float)u4.x, __fmul_rn(asg, su.x), buv.x);
    float u1 = ref_deq((float)u4.y, __fmul_rn(asg, su.y), buv.y);
    float u2 = ref_deq((float)u4.z, __fmul_rn(asg, su.z), buv.z);
    float u3 = ref_deq((float)u4.w, __fmul_rn(asg, su.w), buv.w);

    // h = silu(gate) * up
    float h0 = __fmul_rn(ref_silu(g0), u0);
    float h1 = __fmul_rn(ref_silu(g1), u1);
    float h2 = __fmul_rn(ref_silu(g2), u2);
    float h3 = __fmul_rn(ref_silu(g3), u3);

    // requant: round(h * (1/asd))  (reciprocal-multiply rendition)
    int q0 = ref_quant(h0, inv_asd);
    int q1 = ref_quant(h1, inv_asd);
    int q2 = ref_quant(h2, inv_asd);
    int q3 = ref_quant(h3, inv_asd);

    qh[widx] = (q0 & 255) | ((q1 & 255) << 8) | ((q2 & 255) << 16) | (q3 << 24);
}

// ---------------- launch ----------------
extern "C" void kernel_launch(void* const* d_in, const int* in_sizes, int n_in,
                              void* d_out, int out_size) {
    const float* x       = (const float*)d_in[0];
    const int*   w_gate  = (const int*)d_in[1];
    const int*   w_up    = (const int*)d_in[2];
    const int*   w_down  = (const int*)d_in[3];
    const float* ws_gate = (const float*)d_in[4];
    const float* ws_up   = (const float*)d_in[5];
    const float* ws_down = (const float*)d_in[6];
    const float* b_gate  = (const float*)d_in[7];
    const float* b_up    = (const float*)d_in[8];
    const float* b_down  = (const float*)d_in[9];
    const float* asg     = (const float*)d_in[10];
    const float* asd     = (const float*)d_in[11];
    float* out = (float*)d_out;

    int *qx, *wg, *wu, *wd, *gacc, *uacc, *qh;
    cudaGetSymbolAddress((void**)&qx,   g_qx);
    cudaGetSymbolAddress((void**)&wg,   g_wg);
    cudaGetSymbolAddress((void**)&wu,   g_wu);
    cudaGetSymbolAddress((void**)&wd,   g_wd);
    cudaGetSymbolAddress((void**)&gacc, g_gate);
    cudaGetSymbolAddress((void**)&uacc, g_up);
    cudaGetSymbolAddress((void**)&qh,   g_qh);

    {   // quantize + pack activations
        int n4 = T_TOK * KW_H;
        quant_pack_x_kernel<<<(n4 + 255) / 256, 256>>>(x, asg, qx, n4);
    }
    {   // pack weights
        int n4 = I_DIM * KW_H;
        pack_w_kernel<<<(n4 + 255) / 256, 256>>>(w_gate, wg, n4);
        pack_w_kernel<<<(n4 + 255) / 256, 256>>>(w_up, wu, n4);
        int m4 = H_DIM * KW_I;
        pack_w_kernel<<<(m4 + 255) / 256, 256>>>(w_down, wd, m4);
    }

    // gate / up GEMMs: [T,I] int32 accumulators
    dim3 grid1(I_DIM / 128, T_TOK / 128);
    gemm_s8_kernel<0><<<grid1, 256>>>(qx, wg, KW_H, I_DIM, gacc, nullptr,
                                      nullptr, nullptr, nullptr);
    gemm_s8_kernel<0><<<grid1, 256>>>(qx, wu, KW_H, I_DIM, uacc, nullptr,
                                      nullptr, nullptr, nullptr);

    // SwiGLU + requant + pack
    swiglu_quant_kernel<<<dim3((KW_I + 255) / 256, T_TOK), 256>>>(
        gacc, uacc, ws_gate, ws_up, b_gate, b_up, asg, asd, qh);

    // down GEMM with fused dequant + bias -> fp32 out
    dim3 grid2(H_DIM / 128, T_TOK / 128);
    gemm_s8_kernel<1><<<grid2, 256>>>(qh, wd, KW_I, H_DIM, nullptr, out,
                                      ws_down, b_down, asd);
}

// round 12
// speedup vs baseline: 1.5953x; 1.5953x over previous
#include <cuda_runtime.h>
#include <cstdint>
#include <math.h>

// Problem dims (fixed per reference)
#define T_TOK 8192
#define H_DIM 4096
#define I_DIM 11008
#define KW_H (H_DIM / 4)   // 1024 packed words over K=H
#define KW_I (I_DIM / 4)   // 2752 packed words over K=I

// ---------------- scratch (device globals: no allocations allowed) --------------
__device__ int g_qx[T_TOK * KW_H];                 //  33.5 MB  quantized/packed x
__device__ int g_wg[I_DIM * KW_H];                 //  45 MB    packed w_gate
__device__ int g_wu[I_DIM * KW_H];                 //  45 MB    packed w_up
__device__ int g_wd[H_DIM * KW_I];                 //  45 MB    packed w_down
__device__ int g_qh[T_TOK * KW_I];                 //  90 MB    quantized/packed h

// ================= bit-exact reference numerics (R10-validated) =================
__device__ __forceinline__ float xla_tanh(float x) {
    const float kMax = 7.90531110763549805f;
    float xc = fminf(fmaxf(x, -kMax), kMax);
    float x2 = __fmul_rn(xc, xc);
    float p = -2.76076847742355e-16f;
    p = __fadd_rn(__fmul_rn(p, x2), 2.00018790482477e-13f);
    p = __fadd_rn(__fmul_rn(p, x2), -8.60467152213735e-11f);
    p = __fadd_rn(__fmul_rn(p, x2), 5.12229709037114e-08f);
    p = __fadd_rn(__fmul_rn(p, x2), 1.48572235717979e-05f);
    p = __fadd_rn(__fmul_rn(p, x2), 6.37261928875436e-04f);
    p = __fadd_rn(__fmul_rn(p, x2), 4.89352455891786e-03f);
    p = __fmul_rn(xc, p);
    float q = 1.19825839466702e-06f;
    q = __fadd_rn(__fmul_rn(q, x2), 1.18534705686654e-04f);
    q = __fadd_rn(__fmul_rn(q, x2), 2.26843463243900e-03f);
    q = __fadd_rn(__fmul_rn(q, x2), 4.89352518554385e-03f);
    float t = __fdiv_rn(p, q);
    return (fabsf(x) < 0.0004f) ? x : t;
}
__device__ __forceinline__ float ref_silu(float g) {
    float t   = xla_tanh(__fmul_rn(0.5f, g));
    float sig = __fadd_rn(0.5f, __fmul_rn(0.5f, t));
    return __fmul_rn(g, sig);
}
__device__ __forceinline__ float ref_deq(float acc, float s, float b) {
    return __fadd_rn(__fmul_rn(acc, s), b);
}
__device__ __forceinline__ int ref_quant(float v, float inv_s) {
    float r = rintf(__fmul_rn(v, inv_s));
    return (int)fminf(fmaxf(r, -127.f), 127.f);
}

// ================= baseline-PTX building blocks =================
__device__ __forceinline__ uint32_t smem_u32(const void* p) {
    uint32_t a;
    asm("{ .reg .u64 t; cvta.to.shared.u64 t, %1; cvt.u32.u64 %0, t; }" : "=r"(a) : "l"(p));
    return a;
}
__device__ __forceinline__ void cp16(uint32_t daddr, const void* g) {
    asm volatile("cp.async.cg.shared.global [%0], [%1], 16;" :: "r"(daddr), "l"(g));
}
#define CP_COMMIT() asm volatile("cp.async.commit_group;" ::: "memory")
#define CP_WAIT0()  asm volatile("cp.async.wait_group 0;" ::: "memory")
#define CP_WAIT1()  asm volatile("cp.async.wait_group 1;" ::: "memory")

// IMMA: D(16x8,s32) += A(16x32,s8 row) * B(32x8,s8 col)
__device__ __forceinline__ void mma_s8(int* d, const int* a, const int* b) {
    asm volatile("mma.sync.aligned.m16n8k32.row.col.s32.s8.s8.s32 "
                 "{%0,%1,%2,%3}, {%4,%5,%6,%7}, {%8,%9}, {%0,%1,%2,%3};"
                 : "+r"(d[0]), "+r"(d[1]), "+r"(d[2]), "+r"(d[3])
                 : "r"(a[0]), "r"(a[1]), "r"(a[2]), "r"(a[3]),
                   "r"(b[0]), "r"(b[1]));
}

// smem tile: 128 rows x 64 data bytes, row stride 80 B (20 words) -> the
// quad fragment access pattern (rows g, words t / t+4) is bank-conflict-free.
#define ROW_B   80
#define ROW_W   20
#define TILE_B  (128 * ROW_B)   // 10240

// ================= prep kernels (R10 numerics) =================
__global__ void quant_pack_x_kernel(const float* __restrict__ x,
                                    const float* __restrict__ scale_p,
                                    int* __restrict__ qx, int n4) {
    int idx = blockIdx.x * 256 + threadIdx.x;
    if (idx >= n4) return;
    float inv_s = __fdiv_rn(1.0f, __ldg(scale_p));
    float4 v = reinterpret_cast<const float4*>(x)[idx];
    int q0 = ref_quant(v.x, inv_s);
    int q1 = ref_quant(v.y, inv_s);
    int q2 = ref_quant(v.z, inv_s);
    int q3 = ref_quant(v.w, inv_s);
    qx[idx] = (q0 & 255) | ((q1 & 255) << 8) | ((q2 & 255) << 16) | (q3 << 24);
}
__global__ void pack_w_kernel(const int* __restrict__ w, int* __restrict__ wp, int n4) {
    int idx = blockIdx.x * 256 + threadIdx.x;
    if (idx >= n4) return;
    int4 v = reinterpret_cast<const int4*>(w)[idx];
    wp[idx] = (v.x & 255) | ((v.y & 255) << 8) | ((v.z & 255) << 16) | (v.w << 24);
}

// ================= fused gate+up IMMA GEMM + SwiGLU + requant =================
// Block: 256 thr = 8 warps (4M x 2N).  Tile M=128, N=128, K-step 64 B.
__global__ __launch_bounds__(256, 1)
void gateup_mma_kernel(const int* __restrict__ qx, const int* __restrict__ wg,
                       const int* __restrict__ wu,
                       const float* __restrict__ wsg, const float* __restrict__ wsu,
                       const float* __restrict__ bgp, const float* __restrict__ bup,
                       const float* __restrict__ asg_p, const float* __restrict__ asd_p,
                       int* __restrict__ qh) {
    extern __shared__ char sm[];                 // 2 bufs x 3 tiles x 10240 = 61440
    __shared__ float s_sg[128], s_su[128], s_bg[128], s_bu[128];

    const int tid = threadIdx.x, wid = tid >> 5, lid = tid & 31;
    const int wm = wid >> 1, wn = wid & 1;
    const int g = lid >> 2, t = lid & 3;
    const int bm = blockIdx.y << 7, bn = blockIdx.x << 7;
    const uint32_t su = smem_u32(sm);

    if (tid < 128) {
        s_sg[tid] = wsg[bn + tid]; s_su[tid] = wsu[bn + tid];
        s_bg[tid] = bgp[bn + tid]; s_bu[tid] = bup[bn + tid];
    }

    const int lrow = tid >> 1;           // loader: 2 threads/row
    const int lh   = tid & 1;            // half: words [8h, 8h+8)
    const size_t gA = (size_t)(bm + lrow) * KW_H + lh * 8;
    const size_t gB = (size_t)(bn + lrow) * KW_H + lh * 8;
    const uint32_t sd = su + lrow * ROW_B + lh * 32;

    int cg[2][8][4], cu[2][8][4];
#pragma unroll
    for (int mt = 0; mt < 2; ++mt)
#pragma unroll
        for (int nt = 0; nt < 8; ++nt)
#pragma unroll
            for (int i = 0; i < 4; ++i) { cg[mt][nt][i] = 0; cu[mt][nt][i] = 0; }

    // prologue: step 0 -> buf 0
    {
        cp16(sd,                  qx + gA);      cp16(sd + 16,                  qx + gA + 4);
        cp16(sd + TILE_B,         wg + gB);      cp16(sd + TILE_B + 16,         wg + gB + 4);
        cp16(sd + 2 * TILE_B,     wu + gB);      cp16(sd + 2 * TILE_B + 16,     wu + gB + 4);
        CP_COMMIT();
    }

    const int NSTEP = KW_H / 16;   // 64
    for (int s = 0; s < NSTEP; ++s) {
        const bool more = (s + 1 < NSTEP);
        if (more) {
            const int koff = (s + 1) * 16;
            const uint32_t d2 = sd + ((s + 1) & 1) * (3 * TILE_B);
            cp16(d2,                  qx + gA + koff);  cp16(d2 + 16,                  qx + gA + koff + 4);
            cp16(d2 + TILE_B,         wg + gB + koff);  cp16(d2 + TILE_B + 16,         wg + gB + koff + 4);
            cp16(d2 + 2 * TILE_B,     wu + gB + koff);  cp16(d2 + 2 * TILE_B + 16,     wu + gB + koff + 4);
            CP_COMMIT(); CP_WAIT1();
        } else {
            CP_WAIT0();
        }
        __syncthreads();

        const int* smA = (const int*)(sm + (s & 1) * (3 * TILE_B));
        const int* smG = smA + (TILE_B / 4);
        const int* smU = smA + (TILE_B / 2);
#pragma unroll
        for (int kk = 0; kk < 2; ++kk) {
            int a[2][4];
#pragma unroll
            for (int mt = 0; mt < 2; ++mt) {
                const int r0 = (wm * 32 + mt * 16 + g) * ROW_W + kk * 8 + t;
                a[mt][0] = smA[r0];
                a[mt][1] = smA[r0 + 8 * ROW_W];
                a[mt][2] = smA[r0 + 4];
                a[mt][3] = smA[r0 + 8 * ROW_W + 4];
            }
#pragma unroll
            for (int nt = 0; nt < 8; ++nt) {
                const int c0 = (wn * 64 + nt * 8 + g) * ROW_W + kk * 8 + t;
                int bg2[2] = { smG[c0], smG[c0 + 4] };
                mma_s8(cg[0][nt], a[0], bg2);
                mma_s8(cg[1][nt], a[1], bg2);
                int bu2[2] = { smU[c0], smU[c0 + 4] };
                mma_s8(cu[0][nt], a[0], bu2);
                mma_s8(cu[1][nt], a[1], bu2);
            }
        }
        __syncthreads();
    }

    // ---- fused epilogue (bit-exact R10): dequant -> silu -> mul -> requant ----
    const float asg = __ldg(asg_p);
    const float inv_asd = __fdiv_rn(1.0f, __ldg(asd_p));
    char* stag = sm;                       // 128x128 byte staging (reuses buf 0)
#pragma unroll
    for (int mt = 0; mt < 2; ++mt)
#pragma unroll
        for (int nt = 0; nt < 8; ++nt)
#pragma unroll
            for (int i = 0; i < 4; ++i) {
                int r = wm * 32 + mt * 16 + g + ((i >> 1) << 3);
                int c = wn * 64 + nt * 8 + 2 * t + (i & 1);
                float gv = ref_deq((float)cg[mt][nt][i], __fmul_rn(asg, s_sg[c]), s_bg[c]);
                float uv = ref_deq((float)cu[mt][nt][i], __fmul_rn(asg, s_su[c]), s_bu[c]);
                float h  = __fmul_rn(ref_silu(gv), uv);
                stag[r * 128 + c] = (char)ref_quant(h, inv_asd);
            }
    __syncthreads();
    {
        const int* stw = (const int*)stag;
        const int r = tid >> 1;
        const int w0 = (tid & 1) * 16;
        int* dst = qh + (size_t)(bm + r) * KW_I + (bn >> 2) + w0;
#pragma unroll
        for (int i = 0; i < 16; ++i)
            dst[i] = stw[r * 32 + w0 + i];
    }
}

// ================= down-proj IMMA GEMM + dequant + bias =================
__global__ __launch_bounds__(256, 1)
void down_mma_kernel(const int* __restrict__ qh, const int* __restrict__ wd,
                     const float* __restrict__ wsd, const float* __restrict__ bdp,
                     const float* __restrict__ asd_p, float* __restrict__ out) {
    extern __shared__ char sm[];                 // 2 bufs x 2 tiles x 10240 = 40960
    __shared__ float s_ws[128], s_b[128];

    const int tid = threadIdx.x, wid = tid >> 5, lid = tid & 31;
    const int wm = wid >> 1, wn = wid & 1;
    const int g = lid >> 2, t = lid & 3;
    const int bm = blockIdx.y << 7, bn = blockIdx.x << 7;
    const uint32_t su = smem_u32(sm);

    if (tid < 128) { s_ws[tid] = wsd[bn + tid]; s_b[tid] = bdp[bn + tid]; }

    const int lrow = tid >> 1;
    const int lh   = tid & 1;
    const size_t gA = (size_t)(bm + lrow) * KW_I + lh * 8;
    const size_t gB = (size_t)(bn + lrow) * KW_I + lh * 8;
    const uint32_t sd = su + lrow * ROW_B + lh * 32;

    int c[2][8][4];
#pragma unroll
    for (int mt = 0; mt < 2; ++mt)
#pragma unroll
        for (int nt = 0; nt < 8; ++nt)
#pragma unroll
            for (int i = 0; i < 4; ++i) c[mt][nt][i] = 0;

    {
        cp16(sd,              qh + gA);  cp16(sd + 16,          qh + gA + 4);
        cp16(sd + TILE_B,     wd + gB);  cp16(sd + TILE_B + 16, wd + gB + 4);
        CP_COMMIT();
    }

    const int NSTEP = KW_I / 16;   // 172
    for (int s = 0; s < NSTEP; ++s) {
        const bool more = (s + 1 < NSTEP);
        if (more) {
            const int koff = (s + 1) * 16;
            const uint32_t d2 = sd + ((s + 1) & 1) * (2 * TILE_B);
            cp16(d2,              qh + gA + koff);  cp16(d2 + 16,          qh + gA + koff + 4);
            cp16(d2 + TILE_B,     wd + gB + koff);  cp16(d2 + TILE_B + 16, wd + gB + koff + 4);
            CP_COMMIT(); CP_WAIT1();
        } else {
            CP_WAIT0();
        }
        __syncthreads();

        const int* smA = (const int*)(sm + (s & 1) * (2 * TILE_B));
        const int* smB = smA + (TILE_B / 4);
#pragma unroll
        for (int kk = 0; kk < 2; ++kk) {
            int a[2][4];
#pragma unroll
            for (int mt = 0; mt < 2; ++mt) {
                const int r0 = (wm * 32 + mt * 16 + g) * ROW_W + kk * 8 + t;
                a[mt][0] = smA[r0];
                a[mt][1] = smA[r0 + 8 * ROW_W];
                a[mt][2] = smA[r0 + 4];
                a[mt][3] = smA[r0 + 8 * ROW_W + 4];
            }
#pragma unroll
            for (int nt = 0; nt < 8; ++nt) {
                const int c0 = (wn * 64 + nt * 8 + g) * ROW_W + kk * 8 + t;
                int b2[2] = { smB[c0], smB[c0 + 4] };
                mma_s8(c[0][nt], a[0], b2);
                mma_s8(c[1][nt], a[1], b2);
            }
        }
        __syncthreads();
    }

    // ---- epilogue: dequant + bias -> fp32 (float2 stores, pairs contiguous) ----
    const float asd = __ldg(asd_p);
#pragma unroll
    for (int mt = 0; mt < 2; ++mt)
#pragma unroll
        for (int nt = 0; nt < 8; ++nt) {
            const int cl = wn * 64 + nt * 8 + 2 * t;
            const float s0 = __fmul_rn(asd, s_ws[cl]),     b0 = s_b[cl];
            const float s1 = __fmul_rn(asd, s_ws[cl + 1]), b1 = s_b[cl + 1];
            const int r0 = bm + wm * 32 + mt * 16 + g;
            float2 v0 = { ref_deq((float)c[mt][nt][0], s0, b0),
                          ref_deq((float)c[mt][nt][1], s1, b1) };
            *reinterpret_cast<float2*>(out + (size_t)r0 * H_DIM + bn + cl) = v0;
            float2 v1 = { ref_deq((float)c[mt][nt][2], s0, b0),
                          ref_deq((float)c[mt][nt][3], s1, b1) };
            *reinterpret_cast<float2*>(out + (size_t)(r0 + 8) * H_DIM + bn + cl) = v1;
        }
}

// ================= launch =================
extern "C" void kernel_launch(void* const* d_in, const int* in_sizes, int n_in,
                              void* d_out, int out_size) {
    const float* x       = (const float*)d_in[0];
    const int*   w_gate  = (const int*)d_in[1];
    const int*   w_up    = (const int*)d_in[2];
    const int*   w_down  = (const int*)d_in[3];
    const float* ws_gate = (const float*)d_in[4];
    const float* ws_up   = (const float*)d_in[5];
    const float* ws_down = (const float*)d_in[6];
    const float* b_gate  = (const float*)d_in[7];
    const float* b_up    = (const float*)d_in[8];
    const float* b_down  = (const float*)d_in[9];
    const float* asg     = (const float*)d_in[10];
    const float* asd     = (const float*)d_in[11];
    float* out = (float*)d_out;

    int *qx, *wg, *wu, *wd, *qh;
    cudaGetSymbolAddress((void**)&qx, g_qx);
    cudaGetSymbolAddress((void**)&wg, g_wg);
    cudaGetSymbolAddress((void**)&wu, g_wu);
    cudaGetSymbolAddress((void**)&wd, g_wd);
    cudaGetSymbolAddress((void**)&qh, g_qh);

    cudaFuncSetAttribute(gateup_mma_kernel, cudaFuncAttributeMaxDynamicSharedMemorySize, 61440);
    cudaFuncSetAttribute(down_mma_kernel,   cudaFuncAttributeMaxDynamicSharedMemorySize, 40960);

    {   // quantize + pack activations (reciprocal-multiply rendition — R10-critical)
        int n4 = T_TOK * KW_H;
        quant_pack_x_kernel<<<(n4 + 255) / 256, 256>>>(x, asg, qx, n4);
    }
    {   // pack weights
        int n4 = I_DIM * KW_H;
        pack_w_kernel<<<(n4 + 255) / 256, 256>>>(w_gate, wg, n4);
        pack_w_kernel<<<(n4 + 255) / 256, 256>>>(w_up, wu, n4);
        int m4 = H_DIM * KW_I;
        pack_w_kernel<<<(m4 + 255) / 256, 256>>>(w_down, wd, m4);
    }

    // fused gate+up GEMM + SwiGLU + requant  (IMMA tensor cores)
    gateup_mma_kernel<<<dim3(I_DIM / 128, T_TOK / 128), 256, 61440>>>(
        qx, wg, wu, ws_gate, ws_up, b_gate, b_up, asg, asd, qh);

    // down GEMM + dequant + bias  (IMMA tensor cores)
    down_mma_kernel<<<dim3(H_DIM / 128, T_TOK / 128), 256, 40960>>>(
        qh, wd, ws_down, b_down, asd, out);
}

// round 14
// speedup vs baseline: 1.6289x; 1.0210x over previous
#include <cuda_runtime.h>
#include <cstdint>
#include <math.h>

// Problem dims (fixed per reference)
#define T_TOK 8192
#define H_DIM 4096
#define I_DIM 11008
#define KW_H (H_DIM / 4)   // 1024 packed words over K=H
#define KW_I (I_DIM / 4)   // 2752 packed words over K=I

// ---------------- scratch (device globals: no allocations allowed) --------------
__device__ __align__(256) int g_qx[T_TOK * KW_H];
__device__ __align__(256) int g_wg[I_DIM * KW_H];
__device__ __align__(256) int g_wu[I_DIM * KW_H];
__device__ __align__(256) int g_wd[H_DIM * KW_I];
__device__ __align__(256) int g_qh[T_TOK * KW_I];

// ================= bit-exact reference numerics (R10-validated) =================
__device__ __forceinline__ float xla_tanh(float x) {
    const float kMax = 7.90531110763549805f;
    float xc = fminf(fmaxf(x, -kMax), kMax);
    float x2 = __fmul_rn(xc, xc);
    float p = -2.76076847742355e-16f;
    p = __fadd_rn(__fmul_rn(p, x2), 2.00018790482477e-13f);
    p = __fadd_rn(__fmul_rn(p, x2), -8.60467152213735e-11f);
    p = __fadd_rn(__fmul_rn(p, x2), 5.12229709037114e-08f);
    p = __fadd_rn(__fmul_rn(p, x2), 1.48572235717979e-05f);
    p = __fadd_rn(__fmul_rn(p, x2), 6.37261928875436e-04f);
    p = __fadd_rn(__fmul_rn(p, x2), 4.89352455891786e-03f);
    p = __fmul_rn(xc, p);
    float q = 1.19825839466702e-06f;
    q = __fadd_rn(__fmul_rn(q, x2), 1.18534705686654e-04f);
    q = __fadd_rn(__fmul_rn(q, x2), 2.26843463243900e-03f);
    q = __fadd_rn(__fmul_rn(q, x2), 4.89352518554385e-03f);
    float t = __fdiv_rn(p, q);
    return (fabsf(x) < 0.0004f) ? x : t;
}
__device__ __forceinline__ float ref_silu(float g) {
    float t   = xla_tanh(__fmul_rn(0.5f, g));
    float sig = __fadd_rn(0.5f, __fmul_rn(0.5f, t));
    return __fmul_rn(g, sig);
}
__device__ __forceinline__ float ref_deq(float acc, float s, float b) {
    return __fadd_rn(__fmul_rn(acc, s), b);
}
__device__ __forceinline__ int ref_quant(float v, float inv_s) {
    float r = rintf(__fmul_rn(v, inv_s));
    return (int)fminf(fmaxf(r, -127.f), 127.f);
}

// ================= baseline-PTX building blocks =================
__device__ __forceinline__ uint32_t smem_u32(const void* p) {
    uint32_t a;
    asm("{ .reg .u64 t; cvta.to.shared.u64 t, %1; cvt.u32.u64 %0, t; }" : "=r"(a) : "l"(p));
    return a;
}
__device__ __forceinline__ void cp16(uint32_t daddr, const void* g) {
    asm volatile("cp.async.cg.shared.global [%0], [%1], 16;" :: "r"(daddr), "l"(g));
}
#define CP_COMMIT() asm volatile("cp.async.commit_group;" ::: "memory")
#define CP_WAIT0()  asm volatile("cp.async.wait_group 0;" ::: "memory")
#define CP_WAIT1()  asm volatile("cp.async.wait_group 1;" ::: "memory")

__device__ __forceinline__ void ldsm4(uint32_t* r, uint32_t addr) {
    asm volatile("ldmatrix.sync.aligned.m8n8.x4.shared.b16 {%0,%1,%2,%3}, [%4];"
                 : "=r"(r[0]), "=r"(r[1]), "=r"(r[2]), "=r"(r[3]) : "r"(addr));
}
// IMMA: D(16x8,s32) += A(16x32,s8 row) * B(32x8,s8 col)
__device__ __forceinline__ void mma_s8(int* d, const uint32_t* a, const int b0, const int b1) {
    asm volatile("mma.sync.aligned.m16n8k32.row.col.s32.s8.s8.s32 "
                 "{%0,%1,%2,%3}, {%4,%5,%6,%7}, {%8,%9}, {%0,%1,%2,%3};"
                 : "+r"(d[0]), "+r"(d[1]), "+r"(d[2]), "+r"(d[3])
                 : "r"(a[0]), "r"(a[1]), "r"(a[2]), "r"(a[3]),
                   "r"(b0), "r"(b1));
}

// smem tile: 128 rows x 64 data bytes, row stride 80 B -> ldmatrix phases
// (8 rows/phase) hit 8 distinct 16B slots (80*r mod 128 all distinct).
#define ROW_B   80
#define TILE_B  (128 * ROW_B)   // 10240

// ================= prep kernels (R10 numerics) =================
__global__ void quant_pack_x_kernel(const float* __restrict__ x,
                                    const float* __restrict__ scale_p,
                                    int* __restrict__ qx, int n4) {
    int idx = blockIdx.x * 256 + threadIdx.x;
    if (idx >= n4) return;
    float inv_s = __fdiv_rn(1.0f, __ldg(scale_p));
    float4 v = reinterpret_cast<const float4*>(x)[idx];
    int q0 = ref_quant(v.x, inv_s);
    int q1 = ref_quant(v.y, inv_s);
    int q2 = ref_quant(v.z, inv_s);
    int q3 = ref_quant(v.w, inv_s);
    qx[idx] = (q0 & 255) | ((q1 & 255) << 8) | ((q2 & 255) << 16) | (q3 << 24);
}
__global__ void pack_w_kernel(const int* __restrict__ w, int* __restrict__ wp, int n4) {
    int idx = blockIdx.x * 256 + threadIdx.x;
    if (idx >= n4) return;
    int4 v = reinterpret_cast<const int4*>(w)[idx];
    wp[idx] = (v.x & 255) | ((v.y & 255) << 8) | ((v.z & 255) << 16) | (v.w << 24);
}

// ================= fused gate+up IMMA GEMM + SwiGLU + requant =================
// 512 thr = 16 warps (4M x 4N), warp tile 32x32. Block tile 128x128, K-step 64B.
#define GU_STAGE (3 * TILE_B)    // 30720 per stage (A, Wg, Wu)
__global__ __launch_bounds__(512, 1)
void gateup_mma_kernel(const int* __restrict__ qx, const int* __restrict__ wg,
                       const int* __restrict__ wu,
                       const float* __restrict__ wsg, const float* __restrict__ wsu,
                       const float* __restrict__ bgp, const float* __restrict__ bup,
                       const float* __restrict__ asg_p, const float* __restrict__ asd_p,
                       int* __restrict__ qh) {
    extern __shared__ char sm[];                  // 3 stages x 30720 = 92160
    __shared__ float s_sg[128], s_su[128], s_bg[128], s_bu[128];

    const int tid = threadIdx.x, wid = tid >> 5, lane = tid & 31;
    const int wm = wid >> 2, wn = wid & 3;
    const int g = lane >> 2, t = lane & 3;
    const int bm = blockIdx.y << 7, bn = blockIdx.x << 7;
    const uint32_t su = smem_u32(sm);

    if (tid < 128) {
        s_sg[tid] = wsg[bn + tid]; s_su[tid] = wsu[bn + tid];
        s_bg[tid] = bgp[bn + tid]; s_bu[tid] = bup[bn + tid];
    }

    // loaders: 512 thr, each loads one 16B chunk of each of the 3 tiles
    const int lrow = tid >> 2, lch = tid & 3;
    const size_t gA = (size_t)(bm + lrow) * KW_H + lch * 4;
    const size_t gB = (size_t)(bn + lrow) * KW_H + lch * 4;
    const uint32_t sdo = lrow * ROW_B + lch * 16;

    // ldmatrix per-lane bases (within a stage)
    const int rowL = lane & 15, hi = lane >> 4;
    const uint32_t aO0 = su + (uint32_t)(wm * 32 +  0 + rowL) * ROW_B + hi * 16;
    const uint32_t aO1 = su + (uint32_t)(wm * 32 + 16 + rowL) * ROW_B + hi * 16;
    const uint32_t gO0 = su + TILE_B + (uint32_t)(wn * 32 +  0 + rowL) * ROW_B + hi * 16;
    const uint32_t gO1 = su + TILE_B + (uint32_t)(wn * 32 + 16 + rowL) * ROW_B + hi * 16;
    const uint32_t uO0 = gO0 + TILE_B, uO1 = gO1 + TILE_B;

    int cg[2][4][4], cu[2][4][4];
#pragma unroll
    for (int mt = 0; mt < 2; ++mt)
#pragma unroll
        for (int nt = 0; nt < 4; ++nt)
#pragma unroll
            for (int i = 0; i < 4; ++i) { cg[mt][nt][i] = 0; cu[mt][nt][i] = 0; }

    const int NSTEP = KW_H / 16;   // 64
    // prologue: stages 0,1
#pragma unroll
    for (int s = 0; s < 2; ++s) {
        uint32_t d = su + s * GU_STAGE + sdo;
        int ko = s * 16;
        cp16(d, qx + gA + ko); cp16(d + TILE_B, wg + gB + ko); cp16(d + 2 * TILE_B, wu + gB + ko);
        CP_COMMIT();
    }

    for (int s = 0; s < NSTEP; ++s) {
        if (s + 1 < NSTEP) CP_WAIT1(); else CP_WAIT0();
        __syncthreads();
        if (s + 2 < NSTEP) {
            uint32_t d = su + ((s + 2) % 3) * GU_STAGE + sdo;
            int ko = (s + 2) * 16;
            cp16(d, qx + gA + ko); cp16(d + TILE_B, wg + gB + ko); cp16(d + 2 * TILE_B, wu + gB + ko);
            CP_COMMIT();
        }
        const uint32_t bo = (uint32_t)(s % 3) * GU_STAGE;
#pragma unroll
        for (int kk = 0; kk < 2; ++kk) {
            uint32_t a0[4], a1[4];
            ldsm4(a0, aO0 + bo + kk * 32);
            ldsm4(a1, aO1 + bo + kk * 32);
#pragma unroll
            for (int ng = 0; ng < 2; ++ng) {
                uint32_t b4[4], v4[4];
                ldsm4(b4, (ng ? gO1 : gO0) + bo + kk * 32);
                ldsm4(v4, (ng ? uO1 : uO0) + bo + kk * 32);
                mma_s8(cg[0][ng * 2],     a0, (int)b4[0], (int)b4[2]);
                mma_s8(cg[1][ng * 2],     a1, (int)b4[0], (int)b4[2]);
                mma_s8(cg[0][ng * 2 + 1], a0, (int)b4[1], (int)b4[3]);
                mma_s8(cg[1][ng * 2 + 1], a1, (int)b4[1], (int)b4[3]);
                mma_s8(cu[0][ng * 2],     a0, (int)v4[0], (int)v4[2]);
                mma_s8(cu[1][ng * 2],     a1, (int)v4[0], (int)v4[2]);
                mma_s8(cu[0][ng * 2 + 1], a0, (int)v4[1], (int)v4[3]);
                mma_s8(cu[1][ng * 2 + 1], a1, (int)v4[1], (int)v4[3]);
            }
        }
    }
    __syncthreads();   // protect staging region (overlaps stage buffers)

    // ---- fused epilogue (bit-exact R10): dequant -> silu -> mul -> requant ----
    const float asg = __ldg(asg_p);
    const float inv_asd = __fdiv_rn(1.0f, __ldg(asd_p));
    char* stag = sm;                       // 128x128 byte staging
#pragma unroll
    for (int mt = 0; mt < 2; ++mt)
#pragma unroll
        for (int nt = 0; nt < 4; ++nt)
#pragma unroll
            for (int i = 0; i < 4; ++i) {
                int r = wm * 32 + mt * 16 + g + ((i >> 1) << 3);
                int c = wn * 32 + nt * 8 + 2 * t + (i & 1);
                float gv = ref_deq((float)cg[mt][nt][i], __fmul_rn(asg, s_sg[c]), s_bg[c]);
                float uv = ref_deq((float)cu[mt][nt][i], __fmul_rn(asg, s_su[c]), s_bu[c]);
                float h  = __fmul_rn(ref_silu(gv), uv);
                stag[r * 128 + c] = (char)ref_quant(h, inv_asd);
            }
    __syncthreads();
    {
        const int* stw = (const int*)stag;
        const int r = tid >> 2;
        const int w0 = (tid & 3) * 8;
        int* dst = qh + (size_t)(bm + r) * KW_I + (bn >> 2) + w0;
#pragma unroll
        for (int i = 0; i < 8; ++i)
            dst[i] = stw[r * 32 + w0 + i];
    }
}

// ================= down-proj IMMA GEMM + dequant + bias =================
#define DN_STAGE (2 * TILE_B)    // 20480 per stage (A, Wd)
__global__ __launch_bounds__(512, 1)
void down_mma_kernel(const int* __restrict__ qh, const int* __restrict__ wd,
                     const float* __restrict__ wsd, const float* __restrict__ bdp,
                     const float* __restrict__ asd_p, float* __restrict__ out) {
    extern __shared__ char sm[];                  // 3 stages x 20480 = 61440
    __shared__ float s_ws[128], s_b[128];

    const int tid = threadIdx.x, wid = tid >> 5, lane = tid & 31;
    const int wm = wid >> 2, wn = wid & 3;
    const int g = lane >> 2, t = lane & 3;
    const int bm = blockIdx.y << 7, bn = blockIdx.x << 7;
    const uint32_t su = smem_u32(sm);

    if (tid < 128) { s_ws[tid] = wsd[bn + tid]; s_b[tid] = bdp[bn + tid]; }

    const int lrow = tid >> 2, lch = tid & 3;
    const size_t gA = (size_t)(bm + lrow) * KW_I + lch * 4;
    const size_t gB = (size_t)(bn + lrow) * KW_I + lch * 4;
    const uint32_t sdo = lrow * ROW_B + lch * 16;

    const int rowL = lane & 15, hi = lane >> 4;
    const uint32_t aO0 = su + (uint32_t)(wm * 32 +  0 + rowL) * ROW_B + hi * 16;
    const uint32_t aO1 = su + (uint32_t)(wm * 32 + 16 + rowL) * ROW_B + hi * 16;
    const uint32_t bO0 = su + TILE_B + (uint32_t)(wn * 32 +  0 + rowL) * ROW_B + hi * 16;
    const uint32_t bO1 = su + TILE_B + (uint32_t)(wn * 32 + 16 + rowL) * ROW_B + hi * 16;

    int c[2][4][4];
#pragma unroll
    for (int mt = 0; mt < 2; ++mt)
#pragma unroll
        for (int nt = 0; nt < 4; ++nt)
#pragma unroll
            for (int i = 0; i < 4; ++i) c[mt][nt][i] = 0;

    const int NSTEP = KW_I / 16;   // 172
#pragma unroll
    for (int s = 0; s < 2; ++s) {
        uint32_t d = su + s * DN_STAGE + sdo;
        int ko = s * 16;
        cp16(d, qh + gA + ko); cp16(d + TILE_B, wd + gB + ko);
        CP_COMMIT();
    }

    for (int s = 0; s < NSTEP; ++s) {
        if (s + 1 < NSTEP) CP_WAIT1(); else CP_WAIT0();
        __syncthreads();
        if (s + 2 < NSTEP) {
            uint32_t d = su + ((s + 2) % 3) * DN_STAGE + sdo;
            int ko = (s + 2) * 16;
            cp16(d, qh + gA + ko); cp16(d + TILE_B, wd + gB + ko);
            CP_COMMIT();
        }
        const uint32_t bo = (uint32_t)(s % 3) * DN_STAGE;
#pragma unroll
        for (int kk = 0; kk < 2; ++kk) {
            uint32_t a0[4], a1[4];
            ldsm4(a0, aO0 + bo + kk * 32);
            ldsm4(a1, aO1 + bo + kk * 32);
#pragma unroll
            for (int ng = 0; ng < 2; ++ng) {
                uint32_t b4[4];
                ldsm4(b4, (ng ? bO1 : bO0) + bo + kk * 32);
                mma_s8(c[0][ng * 2],     a0, (int)b4[0], (int)b4[2]);
                mma_s8(c[1][ng * 2],     a1, (int)b4[0], (int)b4[2]);
                mma_s8(c[0][ng * 2 + 1], a0, (int)b4[1], (int)b4[3]);
                mma_s8(c[1][ng * 2 + 1], a1, (int)b4[1], (int)b4[3]);
            }
        }
    }

    // ---- epilogue: dequant + bias -> fp32 (float2 stores) ----
    const float asd = __ldg(asd_p);
#pragma unroll
    for (int mt = 0; mt < 2; ++mt)
#pragma unroll
        for (int nt = 0; nt < 4; ++nt) {
            const int cl = wn * 32 + nt * 8 + 2 * t;
            const float s0 = __fmul_rn(asd, s_ws[cl]),     b0 = s_b[cl];
            const float s1 = __fmul_rn(asd, s_ws[cl + 1]), b1 = s_b[cl + 1];
            const int r0 = bm + wm * 32 + mt * 16 + g;
            float2 v0 = { ref_deq((float)c[mt][nt][0], s0, b0),
                          ref_deq((float)c[mt][nt][1], s1, b1) };
            *reinterpret_cast<float2*>(out + (size_t)r0 * H_DIM + bn + cl) = v0;
            float2 v1 = { ref_deq((float)c[mt][nt][2], s0, b0),
                          ref_deq((float)c[mt][nt][3], s1, b1) };
            *reinterpret_cast<float2*>(out + (size_t)(r0 + 8) * H_DIM + bn + cl) = v1;
        }
}

// ================= launch =================
extern "C" void kernel_launch(void* const* d_in, const int* in_sizes, int n_in,
                              void* d_out, int out_size) {
    const float* x       = (const float*)d_in[0];
    const int*   w_gate  = (const int*)d_in[1];
    const int*   w_up    = (const int*)d_in[2];
    const int*   w_down  = (const int*)d_in[3];
    const float* ws_gate = (const float*)d_in[4];
    const float* ws_up   = (const float*)d_in[5];
    const float* ws_down = (const float*)d_in[6];
    const float* b_gate  = (const float*)d_in[7];
    const float* b_up    = (const float*)d_in[8];
    const float* b_down  = (const float*)d_in[9];
    const float* asg     = (const float*)d_in[10];
    const float* asd     = (const float*)d_in[11];
    float* out = (float*)d_out;

    int *qx, *wg, *wu, *wd, *qh;
    cudaGetSymbolAddress((void**)&qx, g_qx);
    cudaGetSymbolAddress((void**)&wg, g_wg);
    cudaGetSymbolAddress((void**)&wu, g_wu);
    cudaGetSymbolAddress((void**)&wd, g_wd);
    cudaGetSymbolAddress((void**)&qh, g_qh);

    cudaFuncSetAttribute(gateup_mma_kernel, cudaFuncAttributeMaxDynamicSharedMemorySize, 92160);
    cudaFuncSetAttribute(down_mma_kernel,   cudaFuncAttributeMaxDynamicSharedMemorySize, 61440);

    {   // quantize + pack activations (reciprocal-multiply rendition — R10-critical)
        int n4 = T_TOK * KW_H;
        quant_pack_x_kernel<<<(n4 + 255) / 256, 256>>>(x, asg, qx, n4);
    }
    {   // pack weights
        int n4 = I_DIM * KW_H;
        pack_w_kernel<<<(n4 + 255) / 256, 256>>>(w_gate, wg, n4);
        pack_w_kernel<<<(n4 + 255) / 256, 256>>>(w_up, wu, n4);
        int m4 = H_DIM * KW_I;
        pack_w_kernel<<<(m4 + 255) / 256, 256>>>(w_down, wd, m4);
    }

    // fused gate+up GEMM + SwiGLU + requant  (IMMA + ldmatrix)
    gateup_mma_kernel<<<dim3(I_DIM / 128, T_TOK / 128), 512, 92160>>>(
        qx, wg, wu, ws_gate, ws_up, b_gate, b_up, asg, asd, qh);

    // down GEMM + dequant + bias  (IMMA + ldmatrix)
    down_mma_kernel<<<dim3(H_DIM / 128, T_TOK / 128), 512, 61440>>>(
        qh, wd, ws_down, b_down, asd, out);
}

// round 16
// speedup vs baseline: 3.2306x; 1.9834x over previous
#include <cuda_runtime.h>
#include <cuda_fp16.h>
#include <cstdint>
#include <math.h>

// Problem dims (fixed per reference)
#define T_TOK 8192
#define H_DIM 4096
#define I_DIM 11008

// ---------------- scratch (device globals: no allocations allowed) --------------
__device__ __align__(256) __half g_qx_h[T_TOK * (size_t)H_DIM];   //  67 MB
__device__ __align__(256) __half g_wg_h[(size_t)I_DIM * H_DIM];   //  90 MB
__device__ __align__(256) __half g_wu_h[(size_t)I_DIM * H_DIM];   //  90 MB
__device__ __align__(256) __half g_wd_h[(size_t)H_DIM * I_DIM];   //  90 MB
__device__ __align__(256) __half g_qh_h[T_TOK * (size_t)I_DIM];   // 180 MB

// ================= bit-exact reference numerics (R10-validated) =================
__device__ __forceinline__ float xla_tanh(float x) {
    const float kMax = 7.90531110763549805f;
    float xc = fminf(fmaxf(x, -kMax), kMax);
    float x2 = __fmul_rn(xc, xc);
    float p = -2.76076847742355e-16f;
    p = __fadd_rn(__fmul_rn(p, x2), 2.00018790482477e-13f);
    p = __fadd_rn(__fmul_rn(p, x2), -8.60467152213735e-11f);
    p = __fadd_rn(__fmul_rn(p, x2), 5.12229709037114e-08f);
    p = __fadd_rn(__fmul_rn(p, x2), 1.48572235717979e-05f);
    p = __fadd_rn(__fmul_rn(p, x2), 6.37261928875436e-04f);
    p = __fadd_rn(__fmul_rn(p, x2), 4.89352455891786e-03f);
    p = __fmul_rn(xc, p);
    float q = 1.19825839466702e-06f;
    q = __fadd_rn(__fmul_rn(q, x2), 1.18534705686654e-04f);
    q = __fadd_rn(__fmul_rn(q, x2), 2.26843463243900e-03f);
    q = __fadd_rn(__fmul_rn(q, x2), 4.89352518554385e-03f);
    float t = __fdiv_rn(p, q);
    return (fabsf(x) < 0.0004f) ? x : t;
}
__device__ __forceinline__ float ref_silu(float g) {
    float t   = xla_tanh(__fmul_rn(0.5f, g));
    float sig = __fadd_rn(0.5f, __fmul_rn(0.5f, t));
    return __fmul_rn(g, sig);
}
__device__ __forceinline__ float ref_deq(float acc, float s, float b) {
    return __fadd_rn(__fmul_rn(acc, s), b);
}
__device__ __forceinline__ int ref_quant(float v, float inv_s) {
    float r = rintf(__fmul_rn(v, inv_s));
    return (int)fminf(fmaxf(r, -127.f), 127.f);
}

// ================= baseline-PTX building blocks =================
__device__ __forceinline__ uint32_t smem_u32(const void* p) {
    uint32_t a;
    asm("{ .reg .u64 t; cvta.to.shared.u64 t, %1; cvt.u32.u64 %0, t; }" : "=r"(a) : "l"(p));
    return a;
}
__device__ __forceinline__ void cp16(uint32_t daddr, const void* g) {
    asm volatile("cp.async.cg.shared.global [%0], [%1], 16;" :: "r"(daddr), "l"(g));
}
#define CP_COMMIT() asm volatile("cp.async.commit_group;" ::: "memory")
#define CP_WAIT0()  asm volatile("cp.async.wait_group 0;" ::: "memory")
#define CP_WAIT1()  asm volatile("cp.async.wait_group 1;" ::: "memory")

__device__ __forceinline__ void ldsm4(uint32_t* r, uint32_t addr) {
    asm volatile("ldmatrix.sync.aligned.m8n8.x4.shared.b16 {%0,%1,%2,%3}, [%4];"
                 : "=r"(r[0]), "=r"(r[1]), "=r"(r[2]), "=r"(r[3]) : "r"(addr));
}
// HMMA: D(16x8,f32) += A(16x16,f16 row) * B(16x8,f16 col)
__device__ __forceinline__ void mma_f16(float* d, const uint32_t* a, uint32_t b0, uint32_t b1) {
    asm volatile("mma.sync.aligned.m16n8k16.row.col.f32.f16.f16.f32 "
                 "{%0,%1,%2,%3}, {%4,%5,%6,%7}, {%8,%9}, {%0,%1,%2,%3};"
                 : "+f"(d[0]), "+f"(d[1]), "+f"(d[2]), "+f"(d[3])
                 : "r"(a[0]), "r"(a[1]), "r"(a[2]), "r"(a[3]), "r"(b0), "r"(b1));
}

// smem tile: 128 rows x 64 data bytes (32 f16), row stride 80 B ->
// ldmatrix phases (8 rows) hit 8 distinct 16B slots (80*r mod 128 distinct).
#define ROW_B   80
#define TILE_B  (128 * ROW_B)   // 10240

// ================= prep kernels (R10 numerics; emit f16) =================
__global__ void quant_x_h_kernel(const float* __restrict__ x,
                                 const float* __restrict__ scale_p,
                                 __half* __restrict__ qx, int n4) {
    int idx = blockIdx.x * 256 + threadIdx.x;
    if (idx >= n4) return;
    float inv_s = __fdiv_rn(1.0f, __ldg(scale_p));
    float4 v = reinterpret_cast<const float4*>(x)[idx];
    __half h[4];
    h[0] = __float2half_rn((float)ref_quant(v.x, inv_s));
    h[1] = __float2half_rn((float)ref_quant(v.y, inv_s));
    h[2] = __float2half_rn((float)ref_quant(v.z, inv_s));
    h[3] = __float2half_rn((float)ref_quant(v.w, inv_s));
    reinterpret_cast<uint2*>(qx)[idx] = *reinterpret_cast<uint2*>(h);
}
__global__ void w_to_h_kernel(const int* __restrict__ w, __half* __restrict__ wh, int n4) {
    int idx = blockIdx.x * 256 + threadIdx.x;
    if (idx >= n4) return;
    int4 v = reinterpret_cast<const int4*>(w)[idx];
    __half h[4];
    h[0] = __float2half_rn((float)v.x);
    h[1] = __float2half_rn((float)v.y);
    h[2] = __float2half_rn((float)v.z);
    h[3] = __float2half_rn((float)v.w);
    reinterpret_cast<uint2*>(wh)[idx] = *reinterpret_cast<uint2*>(h);
}

// ================= fused gate+up HMMA GEMM + SwiGLU + requant =================
// 512 thr = 16 warps (4M x 4N), warp tile 32x32. Block tile 128x128, K-step 32 f16.
#define GU_STAGE (3 * TILE_B)    // 30720 per stage (A, Wg, Wu)
__global__ __launch_bounds__(512, 1)
void gateup_mma_kernel(const __half* __restrict__ qx, const __half* __restrict__ wg,
                       const __half* __restrict__ wu,
                       const float* __restrict__ wsg, const float* __restrict__ wsu,
                       const float* __restrict__ bgp, const float* __restrict__ bup,
                       const float* __restrict__ asg_p, const float* __restrict__ asd_p,
                       __half* __restrict__ qh) {
    extern __shared__ char sm[];                  // 3 stages x 30720 = 92160
    __shared__ float s_sg[128], s_su[128], s_bg[128], s_bu[128];

    const int tid = threadIdx.x, wid = tid >> 5, lane = tid & 31;
    const int wm = wid >> 2, wn = wid & 3;
    const int g = lane >> 2, t = lane & 3;
    const int bm = blockIdx.y << 7, bn = blockIdx.x << 7;
    const uint32_t su = smem_u32(sm);

    if (tid < 128) {
        s_sg[tid] = wsg[bn + tid]; s_su[tid] = wsu[bn + tid];
        s_bg[tid] = bgp[bn + tid]; s_bu[tid] = bup[bn + tid];
    }

    // loaders: 512 thr, each one 16B chunk (8 f16) per tile
    const int lrow = tid >> 2, lch = tid & 3;
    const size_t gA = (size_t)(bm + lrow) * H_DIM + lch * 8;
    const size_t gB = (size_t)(bn + lrow) * H_DIM + lch * 8;
    const uint32_t sdo = lrow * ROW_B + lch * 16;

    const int rowL = lane & 15, hi = lane >> 4;
    const uint32_t aO0 = su + (uint32_t)(wm * 32 +  0 + rowL) * ROW_B + hi * 16;
    const uint32_t aO1 = su + (uint32_t)(wm * 32 + 16 + rowL) * ROW_B + hi * 16;
    const uint32_t gO0 = su + TILE_B + (uint32_t)(wn * 32 +  0 + rowL) * ROW_B + hi * 16;
    const uint32_t gO1 = su + TILE_B + (uint32_t)(wn * 32 + 16 + rowL) * ROW_B + hi * 16;
    const uint32_t uO0 = gO0 + TILE_B, uO1 = gO1 + TILE_B;

    float cg[2][4][4], cu[2][4][4];
#pragma unroll
    for (int mt = 0; mt < 2; ++mt)
#pragma unroll
        for (int nt = 0; nt < 4; ++nt)
#pragma unroll
            for (int i = 0; i < 4; ++i) { cg[mt][nt][i] = 0.f; cu[mt][nt][i] = 0.f; }

    const int NSTEP = H_DIM / 32;   // 128
#pragma unroll
    for (int s = 0; s < 2; ++s) {
        uint32_t d = su + s * GU_STAGE + sdo;
        int ko = s * 32;
        cp16(d, qx + gA + ko); cp16(d + TILE_B, wg + gB + ko); cp16(d + 2 * TILE_B, wu + gB + ko);
        CP_COMMIT();
    }

    for (int s = 0; s < NSTEP; ++s) {
        if (s + 1 < NSTEP) CP_WAIT1(); else CP_WAIT0();
        __syncthreads();
        if (s + 2 < NSTEP) {
            uint32_t d = su + ((s + 2) % 3) * GU_STAGE + sdo;
            int ko = (s + 2) * 32;
            cp16(d, qx + gA + ko); cp16(d + TILE_B, wg + gB + ko); cp16(d + 2 * TILE_B, wu + gB + ko);
            CP_COMMIT();
        }
        const uint32_t bo = (uint32_t)(s % 3) * GU_STAGE;
#pragma unroll
        for (int kk = 0; kk < 2; ++kk) {       // two k16 halves of the 32-elem step
            const uint32_t off = bo + kk * 32;
            uint32_t a0[4], a1[4];
            ldsm4(a0, aO0 + off);
            ldsm4(a1, aO1 + off);
#pragma unroll
            for (int ng = 0; ng < 2; ++ng) {
                uint32_t b4[4], v4[4];
                ldsm4(b4, (ng ? gO1 : gO0) + off);
                ldsm4(v4, (ng ? uO1 : uO0) + off);
                mma_f16(cg[0][ng * 2],     a0, b4[0], b4[2]);
                mma_f16(cg[1][ng * 2],     a1, b4[0], b4[2]);
                mma_f16(cg[0][ng * 2 + 1], a0, b4[1], b4[3]);
                mma_f16(cg[1][ng * 2 + 1], a1, b4[1], b4[3]);
                mma_f16(cu[0][ng * 2],     a0, v4[0], v4[2]);
                mma_f16(cu[1][ng * 2],     a1, v4[0], v4[2]);
                mma_f16(cu[0][ng * 2 + 1], a0, v4[1], v4[3]);
                mma_f16(cu[1][ng * 2 + 1], a1, v4[1], v4[3]);
            }
        }
    }
    __syncthreads();   // protect staging region (overlaps stage buffers)

    // ---- fused epilogue (bit-exact R10): dequant -> silu -> mul -> requant ----
    const float asg = __ldg(asg_p);
    const float inv_asd = __fdiv_rn(1.0f, __ldg(asd_p));
    __half* stag = (__half*)sm;            // 128x128 f16 staging (32 KB)
#pragma unroll
    for (int mt = 0; mt < 2; ++mt)
#pragma unroll
        for (int nt = 0; nt < 4; ++nt)
#pragma unroll
            for (int i = 0; i < 4; ++i) {
                int r = wm * 32 + mt * 16 + g + ((i >> 1) << 3);
                int c = wn * 32 + nt * 8 + 2 * t + (i & 1);
                float gv = ref_deq(cg[mt][nt][i], __fmul_rn(asg, s_sg[c]), s_bg[c]);
                float uv = ref_deq(cu[mt][nt][i], __fmul_rn(asg, s_su[c]), s_bu[c]);
                float h  = __fmul_rn(ref_silu(gv), uv);
                stag[r * 128 + c] = __float2half_rn((float)ref_quant(h, inv_asd));
            }
    __syncthreads();
    {
        const int r = tid >> 2;
        const __half* srow = stag + r * 128 + (tid & 3) * 32;
        __half* drow = qh + (size_t)(bm + r) * I_DIM + bn + (tid & 3) * 32;
#pragma unroll
        for (int i = 0; i < 4; ++i)
            reinterpret_cast<int4*>(drow)[i] = reinterpret_cast<const int4*>(srow)[i];
    }
}

// ================= down-proj HMMA GEMM + dequant + bias =================
#define DN_STAGE (2 * TILE_B)    // 20480 per stage (A, Wd)
__global__ __launch_bounds__(512, 1)
void down_mma_kernel(const __half* __restrict__ qh, const __half* __restrict__ wd,
                     const float* __restrict__ wsd, const float* __restrict__ bdp,
                     const float* __restrict__ asd_p, float* __restrict__ out) {
    extern __shared__ char sm[];                  // 3 stages x 20480 = 61440
    __shared__ float s_ws[128], s_b[128];

    const int tid = threadIdx.x, wid = tid >> 5, lane = tid & 31;
    const int wm = wid >> 2, wn = wid & 3;
    const int g = lane >> 2, t = lane & 3;
    const int bm = blockIdx.y << 7, bn = blockIdx.x << 7;
    const uint32_t su = smem_u32(sm);

    if (tid < 128) { s_ws[tid] = wsd[bn + tid]; s_b[tid] = bdp[bn + tid]; }

    const int lrow = tid >> 2, lch = tid & 3;
    const size_t gA = (size_t)(bm + lrow) * I_DIM + lch * 8;
    const size_t gB = (size_t)(bn + lrow) * I_DIM + lch * 8;
    const uint32_t sdo = lrow * ROW_B + lch * 16;

    const int rowL = lane & 15, hi = lane >> 4;
    const uint32_t aO0 = su + (uint32_t)(wm * 32 +  0 + rowL) * ROW_B + hi * 16;
    const uint32_t aO1 = su + (uint32_t)(wm * 32 + 16 + rowL) * ROW_B + hi * 16;
    const uint32_t bO0 = su + TILE_B + (uint32_t)(wn * 32 +  0 + rowL) * ROW_B + hi * 16;
    const uint32_t bO1 = su + TILE_B + (uint32_t)(wn * 32 + 16 + rowL) * ROW_B + hi * 16;

    float c[2][4][4];
#pragma unroll
    for (int mt = 0; mt < 2; ++mt)
#pragma unroll
        for (int nt = 0; nt < 4; ++nt)
#pragma unroll
            for (int i = 0; i < 4; ++i) c[mt][nt][i] = 0.f;

    const int NSTEP = I_DIM / 32;   // 344
#pragma unroll
    for (int s = 0; s < 2; ++s) {
        uint32_t d = su + s * DN_STAGE + sdo;
        int ko = s * 32;
        cp16(d, qh + gA + ko); cp16(d + TILE_B, wd + gB + ko);
        CP_COMMIT();
    }

    for (int s = 0; s < NSTEP; ++s) {
        if (s + 1 < NSTEP) CP_WAIT1(); else CP_WAIT0();
        __syncthreads();
        if (s + 2 < NSTEP) {
            uint32_t d = su + ((s + 2) % 3) * DN_STAGE + sdo;
            int ko = (s + 2) * 32;
            cp16(d, qh + gA + ko); cp16(d + TILE_B, wd + gB + ko);
            CP_COMMIT();
        }
        const uint32_t bo = (uint32_t)(s % 3) * DN_STAGE;
#pragma unroll
        for (int kk = 0; kk < 2; ++kk) {
            const uint32_t off = bo + kk * 32;
            uint32_t a0[4], a1[4];
            ldsm4(a0, aO0 + off);
            ldsm4(a1, aO1 + off);
#pragma unroll
            for (int ng = 0; ng < 2; ++ng) {
                uint32_t b4[4];
                ldsm4(b4, (ng ? bO1 : bO0) + off);
                mma_f16(c[0][ng * 2],     a0, b4[0], b4[2]);
                mma_f16(c[1][ng * 2],     a1, b4[0], b4[2]);
                mma_f16(c[0][ng * 2 + 1], a0, b4[1], b4[3]);
                mma_f16(c[1][ng * 2 + 1], a1, b4[1], b4[3]);
            }
        }
    }

    // ---- epilogue: dequant + bias -> fp32 (float2 stores) ----
    const float asd = __ldg(asd_p);
#pragma unroll
    for (int mt = 0; mt < 2; ++mt)
#pragma unroll
        for (int nt = 0; nt < 4; ++nt) {
            const int cl = wn * 32 + nt * 8 + 2 * t;
            const float s0 = __fmul_rn(asd, s_ws[cl]),     b0 = s_b[cl];
            const float s1 = __fmul_rn(asd, s_ws[cl + 1]), b1 = s_b[cl + 1];
            const int r0 = bm + wm * 32 + mt * 16 + g;
            float2 v0 = { ref_deq(c[mt][nt][0], s0, b0),
                          ref_deq(c[mt][nt][1], s1, b1) };
            *reinterpret_cast<float2*>(out + (size_t)r0 * H_DIM + bn + cl) = v0;
            float2 v1 = { ref_deq(c[mt][nt][2], s0, b0),
                          ref_deq(c[mt][nt][3], s1, b1) };
            *reinterpret_cast<float2*>(out + (size_t)(r0 + 8) * H_DIM + bn + cl) = v1;
        }
}

// ================= launch =================
extern "C" void kernel_launch(void* const* d_in, const int* in_sizes, int n_in,
                              void* d_out, int out_size) {
    const float* x       = (const float*)d_in[0];
    const int*   w_gate  = (const int*)d_in[1];
    const int*   w_up    = (const int*)d_in[2];
    const int*   w_down  = (const int*)d_in[3];
    const float* ws_gate = (const float*)d_in[4];
    const float* ws_up   = (const float*)d_in[5];
    const float* ws_down = (const float*)d_in[6];
    const float* b_gate  = (const float*)d_in[7];
    const float* b_up    = (const float*)d_in[8];
    const float* b_down  = (const float*)d_in[9];
    const float* asg     = (const float*)d_in[10];
    const float* asd     = (const float*)d_in[11];
    float* out = (float*)d_out;

    __half *qxh, *wgh, *wuh, *wdh, *qhh;
    cudaGetSymbolAddress((void**)&qxh, g_qx_h);
    cudaGetSymbolAddress((void**)&wgh, g_wg_h);
    cudaGetSymbolAddress((void**)&wuh, g_wu_h);
    cudaGetSymbolAddress((void**)&wdh, g_wd_h);
    cudaGetSymbolAddress((void**)&qhh, g_qh_h);

    cudaFuncSetAttribute(gateup_mma_kernel, cudaFuncAttributeMaxDynamicSharedMemorySize, 92160);
    cudaFuncSetAttribute(down_mma_kernel,   cudaFuncAttributeMaxDynamicSharedMemorySize, 61440);

    {   // quantize x -> f16 ints (reciprocal-multiply rendition — R10-critical)
        int n4 = T_TOK * H_DIM / 4;
        quant_x_h_kernel<<<(n4 + 255) / 256, 256>>>(x, asg, qxh, n4);
    }
    {   // weights int32 -> f16
        int n4 = I_DIM * H_DIM / 4;
        w_to_h_kernel<<<(n4 + 255) / 256, 256>>>(w_gate, wgh, n4);
        w_to_h_kernel<<<(n4 + 255) / 256, 256>>>(w_up, wuh, n4);
        int m4 = H_DIM * I_DIM / 4;
        w_to_h_kernel<<<(m4 + 255) / 256, 256>>>(w_down, wdh, m4);
    }

    // fused gate+up GEMM + SwiGLU + requant  (HMMA f16, exact integer sums)
    gateup_mma_kernel<<<dim3(I_DIM / 128, T_TOK / 128), 512, 92160>>>(
        qxh, wgh, wuh, ws_gate, ws_up, b_gate, b_up, asg, asd, qhh);

    // down GEMM + dequant + bias  (HMMA f16)
    down_mma_kernel<<<dim3(H_DIM / 128, T_TOK / 128), 512, 61440>>>(
        qhh, wdh, ws_down, b_down, asd, out);
}

// round 17
// speedup vs baseline: 3.5098x; 1.0864x over previous
#include <cuda_runtime.h>
#include <cuda_fp16.h>
#include <cstdint>
#include <math.h>

// Problem dims (fixed per reference)
#define T_TOK 8192
#define H_DIM 4096
#define I_DIM 11008

// ---------------- scratch (device globals: no allocations allowed) --------------
__device__ __align__(256) __half g_qx_h[T_TOK * (size_t)H_DIM];   //  67 MB
__device__ __align__(256) __half g_wg_h[(size_t)I_DIM * H_DIM];   //  90 MB
__device__ __align__(256) __half g_wu_h[(size_t)I_DIM * H_DIM];   //  90 MB
__device__ __align__(256) __half g_wd_h[(size_t)H_DIM * I_DIM];   //  90 MB
__device__ __align__(256) __half g_qh_h[T_TOK * (size_t)I_DIM];   // 180 MB

// ================= bit-exact reference numerics (R10-validated) =================
__device__ __forceinline__ float xla_tanh(float x) {
    const float kMax = 7.90531110763549805f;
    float xc = fminf(fmaxf(x, -kMax), kMax);
    float x2 = __fmul_rn(xc, xc);
    float p = -2.76076847742355e-16f;
    p = __fadd_rn(__fmul_rn(p, x2), 2.00018790482477e-13f);
    p = __fadd_rn(__fmul_rn(p, x2), -8.60467152213735e-11f);
    p = __fadd_rn(__fmul_rn(p, x2), 5.12229709037114e-08f);
    p = __fadd_rn(__fmul_rn(p, x2), 1.48572235717979e-05f);
    p = __fadd_rn(__fmul_rn(p, x2), 6.37261928875436e-04f);
    p = __fadd_rn(__fmul_rn(p, x2), 4.89352455891786e-03f);
    p = __fmul_rn(xc, p);
    float q = 1.19825839466702e-06f;
    q = __fadd_rn(__fmul_rn(q, x2), 1.18534705686654e-04f);
    q = __fadd_rn(__fmul_rn(q, x2), 2.26843463243900e-03f);
    q = __fadd_rn(__fmul_rn(q, x2), 4.89352518554385e-03f);
    float t = __fdiv_rn(p, q);
    return (fabsf(x) < 0.0004f) ? x : t;
}
__device__ __forceinline__ float ref_silu(float g) {
    float t   = xla_tanh(__fmul_rn(0.5f, g));
    float sig = __fadd_rn(0.5f, __fmul_rn(0.5f, t));
    return __fmul_rn(g, sig);
}
__device__ __forceinline__ float ref_deq(float acc, float s, float b) {
    return __fadd_rn(__fmul_rn(acc, s), b);
}
__device__ __forceinline__ int ref_quant(float v, float inv_s) {
    float r = rintf(__fmul_rn(v, inv_s));
    return (int)fminf(fmaxf(r, -127.f), 127.f);
}

// ================= baseline-PTX building blocks =================
__device__ __forceinline__ uint32_t smem_u32(const void* p) {
    uint32_t a;
    asm("{ .reg .u64 t; cvta.to.shared.u64 t, %1; cvt.u32.u64 %0, t; }" : "=r"(a) : "l"(p));
    return a;
}
__device__ __forceinline__ void cp16(uint32_t daddr, const void* g) {
    asm volatile("cp.async.cg.shared.global [%0], [%1], 16;" :: "r"(daddr), "l"(g));
}
#define CP_COMMIT() asm volatile("cp.async.commit_group;" ::: "memory")
#define CP_WAIT0()  asm volatile("cp.async.wait_group 0;" ::: "memory")
#define CP_WAIT1()  asm volatile("cp.async.wait_group 1;" ::: "memory")
#define CP_WAIT2()  asm volatile("cp.async.wait_group 2;" ::: "memory")

__device__ __forceinline__ void ldsm4(uint32_t* r, uint32_t addr) {
    asm volatile("ldmatrix.sync.aligned.m8n8.x4.shared.b16 {%0,%1,%2,%3}, [%4];"
                 : "=r"(r[0]), "=r"(r[1]), "=r"(r[2]), "=r"(r[3]) : "r"(addr));
}
// HMMA: D(16x8,f32) += A(16x16,f16 row) * B(16x8,f16 col)
__device__ __forceinline__ void mma_f16(float* d, const uint32_t* a, uint32_t b0, uint32_t b1) {
    asm volatile("mma.sync.aligned.m16n8k16.row.col.f32.f16.f16.f32 "
                 "{%0,%1,%2,%3}, {%4,%5,%6,%7}, {%8,%9}, {%0,%1,%2,%3};"
                 : "+f"(d[0]), "+f"(d[1]), "+f"(d[2]), "+f"(d[3])
                 : "r"(a[0]), "r"(a[1]), "r"(a[2]), "r"(a[3]), "r"(b0), "r"(b1));
}

// smem tile: 128 rows x 64 data bytes (32 f16), row stride 80 B ->
// ldmatrix phases (8 rows) hit 8 distinct 16B slots (80*r mod 128 distinct).
#define ROW_B   80
#define TILE_B  (128 * ROW_B)   // 10240

// ================= prep kernels (R10 numerics; emit f16) =================
__global__ void quant_x_h_kernel(const float* __restrict__ x,
                                 const float* __restrict__ scale_p,
                                 __half* __restrict__ qx, int n4) {
    int idx = blockIdx.x * 256 + threadIdx.x;
    if (idx >= n4) return;
    float inv_s = __fdiv_rn(1.0f, __ldg(scale_p));
    float4 v = reinterpret_cast<const float4*>(x)[idx];
    __half h[4];
    h[0] = __float2half_rn((float)ref_quant(v.x, inv_s));
    h[1] = __float2half_rn((float)ref_quant(v.y, inv_s));
    h[2] = __float2half_rn((float)ref_quant(v.z, inv_s));
    h[3] = __float2half_rn((float)ref_quant(v.w, inv_s));
    reinterpret_cast<uint2*>(qx)[idx] = *reinterpret_cast<uint2*>(h);
}
__global__ void w_to_h_kernel(const int* __restrict__ w, __half* __restrict__ wh, int n4) {
    int idx = blockIdx.x * 256 + threadIdx.x;
    if (idx >= n4) return;
    int4 v = reinterpret_cast<const int4*>(w)[idx];
    __half h[4];
    h[0] = __float2half_rn((float)v.x);
    h[1] = __float2half_rn((float)v.y);
    h[2] = __float2half_rn((float)v.z);
    h[3] = __float2half_rn((float)v.w);
    reinterpret_cast<uint2*>(wh)[idx] = *reinterpret_cast<uint2*>(h);
}

// ================= fused gate+up HMMA GEMM + SwiGLU + requant =================
// 512 thr = 16 warps (4M x 4N), warp tile 32x32. Block tile 128x128, K-step 32 f16.
// Grid: x = M-blocks (fast), y = N-blocks  -> concurrent wave shares qx (L2-
// resident, 67MB) + a few weight tiles; weights stream from DRAM exactly once.
#define GU_STAGE (3 * TILE_B)    // 30720 per stage (A, Wg, Wu)
__global__ __launch_bounds__(512, 1)
void gateup_mma_kernel(const __half* __restrict__ qx, const __half* __restrict__ wg,
                       const __half* __restrict__ wu,
                       const float* __restrict__ wsg, const float* __restrict__ wsu,
                       const float* __restrict__ bgp, const float* __restrict__ bup,
                       const float* __restrict__ asg_p, const float* __restrict__ asd_p,
                       __half* __restrict__ qh) {
    extern __shared__ char sm[];                  // 4 stages x 30720 = 122880
    __shared__ float s_sg[128], s_su[128], s_bg[128], s_bu[128];

    const int tid = threadIdx.x, wid = tid >> 5, lane = tid & 31;
    const int wm = wid >> 2, wn = wid & 3;
    const int g = lane >> 2, t = lane & 3;
    const int bm = blockIdx.x << 7, bn = blockIdx.y << 7;   // M fast, N slow
    const uint32_t su = smem_u32(sm);

    if (tid < 128) {
        s_sg[tid] = wsg[bn + tid]; s_su[tid] = wsu[bn + tid];
        s_bg[tid] = bgp[bn + tid]; s_bu[tid] = bup[bn + tid];
    }

    // loaders: 512 thr, each one 16B chunk (8 f16) per tile
    const int lrow = tid >> 2, lch = tid & 3;
    const size_t gA = (size_t)(bm + lrow) * H_DIM + lch * 8;
    const size_t gB = (size_t)(bn + lrow) * H_DIM + lch * 8;
    const uint32_t sdo = lrow * ROW_B + lch * 16;

    const int rowL = lane & 15, hi = lane >> 4;
    const uint32_t aO0 = su + (uint32_t)(wm * 32 +  0 + rowL) * ROW_B + hi * 16;
    const uint32_t aO1 = su + (uint32_t)(wm * 32 + 16 + rowL) * ROW_B + hi * 16;
    const uint32_t gO0 = su + TILE_B + (uint32_t)(wn * 32 +  0 + rowL) * ROW_B + hi * 16;
    const uint32_t gO1 = su + TILE_B + (uint32_t)(wn * 32 + 16 + rowL) * ROW_B + hi * 16;
    const uint32_t uO0 = gO0 + TILE_B, uO1 = gO1 + TILE_B;

    float cg[2][4][4], cu[2][4][4];
#pragma unroll
    for (int mt = 0; mt < 2; ++mt)
#pragma unroll
        for (int nt = 0; nt < 4; ++nt)
#pragma unroll
            for (int i = 0; i < 4; ++i) { cg[mt][nt][i] = 0.f; cu[mt][nt][i] = 0.f; }

    const int NSTEP = H_DIM / 32;   // 128
#pragma unroll
    for (int s = 0; s < 3; ++s) {   // prologue: stages 0..2
        uint32_t d = su + s * GU_STAGE + sdo;
        int ko = s * 32;
        cp16(d, qx + gA + ko); cp16(d + TILE_B, wg + gB + ko); cp16(d + 2 * TILE_B, wu + gB + ko);
        CP_COMMIT();
    }

    for (int s = 0; s < NSTEP; ++s) {
        if (s + 3 <= NSTEP)      CP_WAIT2();
        else if (s + 2 <= NSTEP) CP_WAIT1();
        else                     CP_WAIT0();
        __syncthreads();
        if (s + 3 < NSTEP) {
            uint32_t d = su + ((s + 3) & 3) * GU_STAGE + sdo;
            int ko = (s + 3) * 32;
            cp16(d, qx + gA + ko); cp16(d + TILE_B, wg + gB + ko); cp16(d + 2 * TILE_B, wu + gB + ko);
            CP_COMMIT();
        }
        const uint32_t bo = (uint32_t)(s & 3) * GU_STAGE;
#pragma unroll
        for (int kk = 0; kk < 2; ++kk) {       // two k16 halves of the 32-elem step
            const uint32_t off = bo + kk * 32;
            uint32_t a0[4], a1[4];
            ldsm4(a0, aO0 + off);
            ldsm4(a1, aO1 + off);
#pragma unroll
            for (int ng = 0; ng < 2; ++ng) {
                uint32_t b4[4], v4[4];
                ldsm4(b4, (ng ? gO1 : gO0) + off);
                ldsm4(v4, (ng ? uO1 : uO0) + off);
                mma_f16(cg[0][ng * 2],     a0, b4[0], b4[2]);
                mma_f16(cg[1][ng * 2],     a1, b4[0], b4[2]);
                mma_f16(cg[0][ng * 2 + 1], a0, b4[1], b4[3]);
                mma_f16(cg[1][ng * 2 + 1], a1, b4[1], b4[3]);
                mma_f16(cu[0][ng * 2],     a0, v4[0], v4[2]);
                mma_f16(cu[1][ng * 2],     a1, v4[0], v4[2]);
                mma_f16(cu[0][ng * 2 + 1], a0, v4[1], v4[3]);
                mma_f16(cu[1][ng * 2 + 1], a1, v4[1], v4[3]);
            }
        }
    }
    __syncthreads();   // protect staging region (overlaps stage buffers)

    // ---- fused epilogue (bit-exact R10): dequant -> silu -> mul -> requant ----
    const float asg = __ldg(asg_p);
    const float inv_asd = __fdiv_rn(1.0f, __ldg(asd_p));
    __half* stag = (__half*)sm;            // 128x128 f16 staging (32 KB)
#pragma unroll
    for (int mt = 0; mt < 2; ++mt)
#pragma unroll
        for (int nt = 0; nt < 4; ++nt)
#pragma unroll
            for (int i = 0; i < 4; ++i) {
                int r = wm * 32 + mt * 16 + g + ((i >> 1) << 3);
                int c = wn * 32 + nt * 8 + 2 * t + (i & 1);
                float gv = ref_deq(cg[mt][nt][i], __fmul_rn(asg, s_sg[c]), s_bg[c]);
                float uv = ref_deq(cu[mt][nt][i], __fmul_rn(asg, s_su[c]), s_bu[c]);
                float h  = __fmul_rn(ref_silu(gv), uv);
                stag[r * 128 + c] = __float2half_rn((float)ref_quant(h, inv_asd));
            }
    __syncthreads();
    {
        const int r = tid >> 2;
        const __half* srow = stag + r * 128 + (tid & 3) * 32;
        __half* drow = qh + (size_t)(bm + r) * I_DIM + bn + (tid & 3) * 32;
#pragma unroll
        for (int i = 0; i < 4; ++i)
            reinterpret_cast<int4*>(drow)[i] = reinterpret_cast<const int4*>(srow)[i];
    }
}

// ================= down-proj HMMA GEMM + dequant + bias =================
// Grid: x = N-blocks (32, fast), y = M-blocks -> wd (90MB) L2-resident, qh read once.
#define DN_STAGE (2 * TILE_B)    // 20480 per stage (A, Wd)
__global__ __launch_bounds__(512, 1)
void down_mma_kernel(const __half* __restrict__ qh, const __half* __restrict__ wd,
                     const float* __restrict__ wsd, const float* __restrict__ bdp,
                     const float* __restrict__ asd_p, float* __restrict__ out) {
    extern __shared__ char sm[];                  // 4 stages x 20480 = 81920
    __shared__ float s_ws[128], s_b[128];

    const int tid = threadIdx.x, wid = tid >> 5, lane = tid & 31;
    const int wm = wid >> 2, wn = wid & 3;
    const int g = lane >> 2, t = lane & 3;
    const int bm = blockIdx.y << 7, bn = blockIdx.x << 7;
    const uint32_t su = smem_u32(sm);

    if (tid < 128) { s_ws[tid] = wsd[bn + tid]; s_b[tid] = bdp[bn + tid]; }

    const int lrow = tid >> 2, lch = tid & 3;
    const size_t gA = (size_t)(bm + lrow) * I_DIM + lch * 8;
    const size_t gB = (size_t)(bn + lrow) * I_DIM + lch * 8;
    const uint32_t sdo = lrow * ROW_B + lch * 16;

    const int rowL = lane & 15, hi = lane >> 4;
    const uint32_t aO0 = su + (uint32_t)(wm * 32 +  0 + rowL) * ROW_B + hi * 16;
    const uint32_t aO1 = su + (uint32_t)(wm * 32 + 16 + rowL) * ROW_B + hi * 16;
    const uint32_t bO0 = su + TILE_B + (uint32_t)(wn * 32 +  0 + rowL) * ROW_B + hi * 16;
    const uint32_t bO1 = su + TILE_B + (uint32_t)(wn * 32 + 16 + rowL) * ROW_B + hi * 16;

    float c[2][4][4];
#pragma unroll
    for (int mt = 0; mt < 2; ++mt)
#pragma unroll
        for (int nt = 0; nt < 4; ++nt)
#pragma unroll
            for (int i = 0; i < 4; ++i) c[mt][nt][i] = 0.f;

    const int NSTEP = I_DIM / 32;   // 344
#pragma unroll
    for (int s = 0; s < 3; ++s) {
        uint32_t d = su + s * DN_STAGE + sdo;
        int ko = s * 32;
        cp16(d, qh + gA + ko); cp16(d + TILE_B, wd + gB + ko);
        CP_COMMIT();
    }

    for (int s = 0; s < NSTEP; ++s) {
        if (s + 3 <= NSTEP)      CP_WAIT2();
        else if (s + 2 <= NSTEP) CP_WAIT1();
        else                     CP_WAIT0();
        __syncthreads();
        if (s + 3 < NSTEP) {
            uint32_t d = su + ((s + 3) & 3) * DN_STAGE + sdo;
            int ko = (s + 3) * 32;
            cp16(d, qh + gA + ko); cp16(d + TILE_B, wd + gB + ko);
            CP_COMMIT();
        }
        const uint32_t bo = (uint32_t)(s & 3) * DN_STAGE;
#pragma unroll
        for (int kk = 0; kk < 2; ++kk) {
            const uint32_t off = bo + kk * 32;
            uint32_t a0[4], a1[4];
            ldsm4(a0, aO0 + off);
            ldsm4(a1, aO1 + off);
#pragma unroll
            for (int ng = 0; ng < 2; ++ng) {
                uint32_t b4[4];
                ldsm4(b4, (ng ? bO1 : bO0) + off);
                mma_f16(c[0][ng * 2],     a0, b4[0], b4[2]);
                mma_f16(c[1][ng * 2],     a1, b4[0], b4[2]);
                mma_f16(c[0][ng * 2 + 1], a0, b4[1], b4[3]);
                mma_f16(c[1][ng * 2 + 1], a1, b4[1], b4[3]);
            }
        }
    }

    // ---- epilogue: dequant + bias -> fp32 (float2 stores) ----
    const float asd = __ldg(asd_p);
#pragma unroll
    for (int mt = 0; mt < 2; ++mt)
#pragma unroll
        for (int nt = 0; nt < 4; ++nt) {
            const int cl = wn * 32 + nt * 8 + 2 * t;
            const float s0 = __fmul_rn(asd, s_ws[cl]),     b0 = s_b[cl];
            const float s1 = __fmul_rn(asd, s_ws[cl + 1]), b1 = s_b[cl + 1];
            const int r0 = bm + wm * 32 + mt * 16 + g;
            float2 v0 = { ref_deq(c[mt][nt][0], s0, b0),
                          ref_deq(c[mt][nt][1], s1, b1) };
            *reinterpret_cast<float2*>(out + (size_t)r0 * H_DIM + bn + cl) = v0;
            float2 v1 = { ref_deq(c[mt][nt][2], s0, b0),
                          ref_deq(c[mt][nt][3], s1, b1) };
            *reinterpret_cast<float2*>(out + (size_t)(r0 + 8) * H_DIM + bn + cl) = v1;
        }
}

// ================= launch =================
extern "C" void kernel_launch(void* const* d_in, const int* in_sizes, int n_in,
                              void* d_out, int out_size) {
    const float* x       = (const float*)d_in[0];
    const int*   w_gate  = (const int*)d_in[1];
    const int*   w_up    = (const int*)d_in[2];
    const int*   w_down  = (const int*)d_in[3];
    const float* ws_gate = (const float*)d_in[4];
    const float* ws_up   = (const float*)d_in[5];
    const float* ws_down = (const float*)d_in[6];
    const float* b_gate  = (const float*)d_in[7];
    const float* b_up    = (const float*)d_in[8];
    const float* b_down  = (const float*)d_in[9];
    const float* asg     = (const float*)d_in[10];
    const float* asd     = (const float*)d_in[11];
    float* out = (float*)d_out;

    __half *qxh, *wgh, *wuh, *wdh, *qhh;
    cudaGetSymbolAddress((void**)&qxh, g_qx_h);
    cudaGetSymbolAddress((void**)&wgh, g_wg_h);
    cudaGetSymbolAddress((void**)&wuh, g_wu_h);
    cudaGetSymbolAddress((void**)&wdh, g_wd_h);
    cudaGetSymbolAddress((void**)&qhh, g_qh_h);

    cudaFuncSetAttribute(gateup_mma_kernel, cudaFuncAttributeMaxDynamicSharedMemorySize, 122880);
    cudaFuncSetAttribute(down_mma_kernel,   cudaFuncAttributeMaxDynamicSharedMemorySize, 81920);

    {   // quantize x -> f16 ints (reciprocal-multiply rendition — R10-critical)
        int n4 = T_TOK * H_DIM / 4;
        quant_x_h_kernel<<<(n4 + 255) / 256, 256>>>(x, asg, qxh, n4);
    }
    {   // weights int32 -> f16
        int n4 = I_DIM * H_DIM / 4;
        w_to_h_kernel<<<(n4 + 255) / 256, 256>>>(w_gate, wgh, n4);
        w_to_h_kernel<<<(n4 + 255) / 256, 256>>>(w_up, wuh, n4);
        int m4 = H_DIM * I_DIM / 4;
        w_to_h_kernel<<<(m4 + 255) / 256, 256>>>(w_down, wdh, m4);
    }

    // fused gate+up GEMM + SwiGLU + requant  (HMMA f16; M-fast grid for L2 reuse)
    gateup_mma_kernel<<<dim3(T_TOK / 128, I_DIM / 128), 512, 122880>>>(
        qxh, wgh, wuh, ws_gate, ws_up, b_gate, b_up, asg, asd, qhh);

    // down GEMM + dequant + bias  (HMMA f16)
    down_mma_kernel<<<dim3(H_DIM / 128, T_TOK / 128), 512, 81920>>>(
        qhh, wdh, ws_down, b_down, asd, out);
}